// round 16
// baseline (speedup 1.0000x reference)
#include <cuda_runtime.h>
#include <cstdint>

#define NMAX 50000
#define EMAX 400000
#define HEADS 4
#define DIM 64
#define HD 256   // HEADS*DIM

#define PAD 68                        // padded row length
#define AS_FLOATS (128 * PAD)         // A tile (float)
#define BS_WORDS  (64 * PAD)          // one B plane (uint32)
#define GEMM_SMEM_B ((AS_FLOATS + 2 * BS_WORDS) * 4)   // 69,632 bytes

// ---------------- scratch (device globals; no allocation) ----------------
__device__ float    g_agg   [(size_t)NMAX * HD];   // per-head weighted x sums [N,4,64]
__device__ float    g_ssrc  [(size_t)NMAX * HEADS];
__device__ float    g_sdst  [(size_t)NMAX * HEADS];
__device__ int      g_cnt   [NMAX];
__device__ int      g_off   [NMAX + 1];
__device__ int      g_cursor[NMAX];
__device__ int      g_esrc  [EMAX];
__device__ float    g_ealpha[(size_t)EMAX * HEADS];
__device__ uint32_t g_wchi  [64 * HD];             // folded weight tf32-hi [64][256]
__device__ uint32_t g_wclo  [64 * HD];             // folded weight tf32-lo
__device__ float    g_vv    [8 * DIM];             // score vectors: src h0-3, dst h0-3

// ---------------- tf32 mma helpers ----------------
__device__ __forceinline__ uint32_t f2tf32(float x) {
    uint32_t r;
    asm("cvt.rna.tf32.f32 %0, %1;" : "=r"(r) : "f"(x));
    return r;
}
__device__ __forceinline__ void hilo(float v, uint32_t& hi, uint32_t& lo) {
    hi = f2tf32(v);
    lo = f2tf32(v - __uint_as_float(hi));
}
__device__ __forceinline__ void mma_tf32(float& d0, float& d1, float& d2, float& d3,
                                         uint32_t a0, uint32_t a1, uint32_t a2, uint32_t a3,
                                         uint32_t b0, uint32_t b1) {
    asm("mma.sync.aligned.m16n8k8.row.col.f32.tf32.tf32.f32 "
        "{%0,%1,%2,%3}, {%4,%5,%6,%7}, {%8,%9}, {%0,%1,%2,%3};"
        : "+f"(d0), "+f"(d1), "+f"(d2), "+f"(d3)
        : "r"(a0), "r"(a1), "r"(a2), "r"(a3), "r"(b0), "r"(b1));
}

// ---------------- zero histogram ----------------
__global__ void k_hzero(int* __restrict__ cnt, int n) {
    int i = blockIdx.x * blockDim.x + threadIdx.x;
    if (i < n) cnt[i] = 0;
}

// ---------------- histogram of dst ----------------
__global__ void k_hist(const int* __restrict__ ei, int* __restrict__ cnt, int E) {
    int e = blockIdx.x * blockDim.x + threadIdx.x;
    if (e < E) atomicAdd(&cnt[ei[e]], 1);
}

// ---------------- single-block exclusive scan, 4 elems/thread ----------------
__global__ __launch_bounds__(1024) void k_scan(const int* __restrict__ cnt,
                                               int* __restrict__ off,
                                               int* __restrict__ cursor, int n)
{
    __shared__ int warpsum[32];
    const int tid  = threadIdx.x;
    const int lane = tid & 31;
    const int wid  = tid >> 5;
    int base = 0;
    for (int chunk = 0; chunk < n; chunk += 4096) {
        int i0 = chunk + tid * 4;
        int v0 = (i0 + 0 < n) ? cnt[i0 + 0] : 0;
        int v1 = (i0 + 1 < n) ? cnt[i0 + 1] : 0;
        int v2 = (i0 + 2 < n) ? cnt[i0 + 2] : 0;
        int v3 = (i0 + 3 < n) ? cnt[i0 + 3] : 0;
        int s = v0 + v1 + v2 + v3;
        int x = s;
        #pragma unroll
        for (int o = 1; o < 32; o <<= 1) {
            int y = __shfl_up_sync(0xffffffffu, x, o);
            if (lane >= o) x += y;
        }
        if (lane == 31) warpsum[wid] = x;
        __syncthreads();
        if (wid == 0) {
            int w = warpsum[lane];
            #pragma unroll
            for (int o = 1; o < 32; o <<= 1) {
                int y = __shfl_up_sync(0xffffffffu, w, o);
                if (lane >= o) w += y;
            }
            warpsum[lane] = w;
        }
        __syncthreads();
        int excl = x - s + (wid > 0 ? warpsum[wid - 1] : 0) + base;
        if (i0 + 0 < n) { off[i0 + 0] = excl; cursor[i0 + 0] = excl; } excl += v0;
        if (i0 + 1 < n) { off[i0 + 1] = excl; cursor[i0 + 1] = excl; } excl += v1;
        if (i0 + 2 < n) { off[i0 + 2] = excl; cursor[i0 + 2] = excl; } excl += v2;
        if (i0 + 3 < n) { off[i0 + 3] = excl; cursor[i0 + 3] = excl; }
        int total = warpsum[31];
        __syncthreads();
        base += total;
    }
    if (tid == 0) off[n] = base;
}

// ---------------- prep: fold weights (hi/lo planes) + score vectors ----------------
__global__ __launch_bounds__(256) void k_prep(
    const float* __restrict__ Wlin,  // [256,64]
    const float* __restrict__ Wout,  // [64,256]
    const float* __restrict__ asrc, const float* __restrict__ adst,
    uint32_t* __restrict__ wchi, uint32_t* __restrict__ wclo,
    float* __restrict__ vv)
{
    __shared__ float Wl[64][65];   // Wl[c][k] = W_lin[h*64+c][k]
    __shared__ float Wo[64][65];   // Wo[d][c] = W_out[d][h*64+c]
    const int h = blockIdx.x;
    const int t = threadIdx.x;
    #pragma unroll
    for (int it = 0; it < 16; ++it) {
        int idx = t + it * 256;
        int r = idx >> 6, c = idx & 63;
        Wl[r][c] = Wlin[(size_t)(h * 64 + r) * DIM + c];
        Wo[r][c] = Wout[(size_t)r * HD + h * 64 + c];
    }
    __syncthreads();

    // Wc[d][h*64+k] = sum_c Wo[d][c] * Wl[c][k]  -> stored as tf32 hi/lo planes
    int d = t >> 2, ks0 = (t & 3) * 16;
    float accv[16] = {};
    for (int c = 0; c < 64; ++c) {
        float wo = Wo[d][c];
        #pragma unroll
        for (int kk = 0; kk < 16; ++kk) accv[kk] += wo * Wl[c][ks0 + kk];
    }
    #pragma unroll
    for (int kk = 0; kk < 16; ++kk) {
        uint32_t hh, ll;
        hilo(accv[kk], hh, ll);
        wchi[(size_t)d * HD + h * 64 + ks0 + kk] = hh;
        wclo[(size_t)d * HD + h * 64 + ks0 + kk] = ll;
    }

    // v_src[h][k] = sum_c Wl[c][k] * asrc[h][c]; v_dst likewise
    if (t < 64) {
        float s = 0.f;
        for (int c = 0; c < 64; ++c) s += Wl[c][t] * __ldg(asrc + h * DIM + c);
        vv[h * DIM + t] = s;
    } else if (t < 128) {
        int k = t - 64;
        float s = 0.f;
        for (int c = 0; c < 64; ++c) s += Wl[c][k] * __ldg(adst + h * DIM + c);
        vv[(4 + h) * DIM + k] = s;
    }
}

// ---------------- scores: 2 threads per node (half row each) ----------------
__global__ __launch_bounds__(256) void k_scores(
    const float* __restrict__ x, const float* __restrict__ vv,
    float* __restrict__ ssrc, float* __restrict__ sdst, int n)
{
    __shared__ float4 vs[8][16];
    int t = threadIdx.x;
    if (t < 128) {
        int v = t >> 4, k4 = t & 15;
        vs[v][k4] = *(const float4*)(vv + v * DIM + k4 * 4);
    }
    __syncthreads();
    int idx = blockIdx.x * 256 + t;
    if (idx >= 2 * n) return;
    int node = idx >> 1;
    int half = idx & 1;
    const float4* xr = (const float4*)(x + (size_t)node * DIM) + half * 8;
    float acc[8] = {};
    #pragma unroll
    for (int k4 = 0; k4 < 8; ++k4) {
        float4 xv = xr[k4];
        #pragma unroll
        for (int v = 0; v < 8; ++v) {
            float4 w = vs[v][half * 8 + k4];
            acc[v] += xv.x * w.x + xv.y * w.y + xv.z * w.z + xv.w * w.w;
        }
    }
    #pragma unroll
    for (int v = 0; v < 8; ++v)
        acc[v] += __shfl_xor_sync(0xffffffffu, acc[v], 1);
    if (half == 0)
        *(float4*)(ssrc + (size_t)node * 4) = make_float4(acc[0], acc[1], acc[2], acc[3]);
    else
        *(float4*)(sdst + (size_t)node * 4) = make_float4(acc[4], acc[5], acc[6], acc[7]);
}

// ---------------- scatter edges into dst-sorted order, alpha inline ----------------
__global__ void k_scatter(const int* __restrict__ ei,
                          const float* __restrict__ ssrc, const float* __restrict__ sdst,
                          int* __restrict__ cursor,
                          int* __restrict__ esrc, float* __restrict__ ealpha, int E)
{
    int e = blockIdx.x * blockDim.x + threadIdx.x;
    if (e >= E) return;
    int i = ei[e];        // dst
    int j = ei[E + e];    // src
    float4 sd = *(const float4*)(sdst + (size_t)i * 4);
    float4 ss = *(const float4*)(ssrc + (size_t)j * 4);
    float a0 = sd.x + ss.x; a0 = a0 > 0.f ? a0 : 0.2f * a0;
    float a1 = sd.y + ss.y; a1 = a1 > 0.f ? a1 : 0.2f * a1;
    float a2 = sd.z + ss.z; a2 = a2 > 0.f ? a2 : 0.2f * a2;
    float a3 = sd.w + ss.w; a3 = a3 > 0.f ? a3 : 0.2f * a3;
    int pos = atomicAdd(&cursor[i], 1);
    esrc[pos] = j;
    *(float4*)(ealpha + (size_t)pos * 4) =
        make_float4(expf(a0), expf(a1), expf(a2), expf(a3));
}

// ---------------- aggregation of raw x: warp per dst, 2-edge pipeline ----------------
__global__ __launch_bounds__(256) void k_agg_x(
    const int* __restrict__ off, const int* __restrict__ esrc,
    const float* __restrict__ ealpha, const float* __restrict__ x,
    float* __restrict__ agg, int n)
{
    int w    = (blockIdx.x * blockDim.x + threadIdx.x) >> 5;
    int lane = threadIdx.x & 31;
    if (w >= n) return;
    int beg = off[w], end = off[w + 1];
    float2 acc[4] = {};
    float  dsum[4] = {};

    int e = beg;
    for (; e + 1 < end; e += 2) {
        int j0 = esrc[e];
        int j1 = esrc[e + 1];
        float4 a0 = *(const float4*)(ealpha + (size_t)e * 4);
        float4 a1 = *(const float4*)(ealpha + (size_t)(e + 1) * 4);
        float2 x0 = *(const float2*)(x + (size_t)j0 * DIM + lane * 2);
        float2 x1 = *(const float2*)(x + (size_t)j1 * DIM + lane * 2);
        acc[0].x += a0.x * x0.x + a1.x * x1.x; acc[0].y += a0.x * x0.y + a1.x * x1.y;
        acc[1].x += a0.y * x0.x + a1.y * x1.x; acc[1].y += a0.y * x0.y + a1.y * x1.y;
        acc[2].x += a0.z * x0.x + a1.z * x1.x; acc[2].y += a0.z * x0.y + a1.z * x1.y;
        acc[3].x += a0.w * x0.x + a1.w * x1.x; acc[3].y += a0.w * x0.y + a1.w * x1.y;
        dsum[0] += a0.x + a1.x; dsum[1] += a0.y + a1.y;
        dsum[2] += a0.z + a1.z; dsum[3] += a0.w + a1.w;
    }
    if (e < end) {
        int j0 = esrc[e];
        float4 a0 = *(const float4*)(ealpha + (size_t)e * 4);
        float2 x0 = *(const float2*)(x + (size_t)j0 * DIM + lane * 2);
        acc[0].x += a0.x * x0.x; acc[0].y += a0.x * x0.y;
        acc[1].x += a0.y * x0.x; acc[1].y += a0.y * x0.y;
        acc[2].x += a0.z * x0.x; acc[2].y += a0.z * x0.y;
        acc[3].x += a0.w * x0.x; acc[3].y += a0.w * x0.y;
        dsum[0] += a0.x; dsum[1] += a0.y; dsum[2] += a0.z; dsum[3] += a0.w;
    }
    #pragma unroll
    for (int h = 0; h < 4; ++h) {
        float inv = 1.0f / (dsum[h] + 1e-9f);
        *(float2*)(agg + (size_t)w * HD + h * DIM + lane * 2) =
            make_float2(acc[h].x * inv, acc[h].y * inv);
    }
}

// ---------------- GEMM2 (tf32 mma, Wc hi/lo preconverted): out = LN(ELU(aggx@Wc^T+b)+x) ----------------
__global__ __launch_bounds__(256) void k_gemm2(
    const float* __restrict__ A,          // aggx [M,256]
    const uint32_t* __restrict__ wchi,    // [64,256] tf32 hi
    const uint32_t* __restrict__ wclo,    // [64,256] tf32 lo
    const float* __restrict__ x,
    const float* __restrict__ bias,
    const float* __restrict__ lng, const float* __restrict__ lnb,
    float* __restrict__ out, int M)
{
    extern __shared__ float sm[];
    float*    As  = sm;                                  // [128][PAD]
    uint32_t* Bhi = (uint32_t*)(sm + AS_FLOATS);
    uint32_t* Blo = Bhi + BS_WORDS;
    const int t    = threadIdx.x;
    const int lane = t & 31;
    const int w    = t >> 5;
    const int gid  = lane >> 2;
    const int tid4 = lane & 3;
    const int m0   = blockIdx.x * 128;

    float acc[8][4] = {};
    const int r0 = w * 16 + gid;
    const int r1 = r0 + 8;

    for (int kc = 0; kc < HD; kc += 64) {
        #pragma unroll
        for (int it = 0; it < 8; ++it) {
            int idx = t + it * 256;
            int row = idx >> 4;
            int k4  = (idx & 15) * 4;
            float4 v = make_float4(0.f, 0.f, 0.f, 0.f);
            int gr = m0 + row;
            if (gr < M) v = *(const float4*)(A + (size_t)gr * HD + kc + k4);
            *(float4*)&As[row * PAD + k4] = v;
        }
        #pragma unroll
        for (int it = 0; it < 4; ++it) {
            int idx = t + it * 256;
            int nr  = idx >> 4;
            int k4  = (idx & 15) * 4;
            uint4 vh = *(const uint4*)(wchi + (size_t)nr * HD + kc + k4);
            uint4 vl = *(const uint4*)(wclo + (size_t)nr * HD + kc + k4);
            *(uint4*)&Bhi[nr * PAD + k4] = vh;
            *(uint4*)&Blo[nr * PAD + k4] = vl;
        }
        __syncthreads();

        #pragma unroll
        for (int ks = 0; ks < 8; ++ks) {
            int c0 = ks * 8 + tid4;
            int c1 = c0 + 4;
            uint32_t ah[4], al[4];
            hilo(As[r0 * PAD + c0], ah[0], al[0]);
            hilo(As[r1 * PAD + c0], ah[1], al[1]);
            hilo(As[r0 * PAD + c1], ah[2], al[2]);
            hilo(As[r1 * PAD + c1], ah[3], al[3]);
            #pragma unroll
            for (int nt = 0; nt < 8; ++nt) {
                int bi = (nt * 8 + gid) * PAD;
                uint32_t bh0 = Bhi[bi + c0], bl0 = Blo[bi + c0];
                uint32_t bh1 = Bhi[bi + c1], bl1 = Blo[bi + c1];
                mma_tf32(acc[nt][0], acc[nt][1], acc[nt][2], acc[nt][3],
                         ah[0], ah[1], ah[2], ah[3], bh0, bh1);
                mma_tf32(acc[nt][0], acc[nt][1], acc[nt][2], acc[nt][3],
                         ah[0], ah[1], ah[2], ah[3], bl0, bl1);
                mma_tf32(acc[nt][0], acc[nt][1], acc[nt][2], acc[nt][3],
                         al[0], al[1], al[2], al[3], bh0, bh1);
            }
        }
        __syncthreads();
    }

    // epilogue: bias + ELU + residual + LayerNorm; two rows per thread
    int gr0 = m0 + r0;
    int gr1 = m0 + r1;
    float y0[16], y1[16];
    float s0 = 0.f, q0 = 0.f, s1 = 0.f, q1 = 0.f;
    #pragma unroll
    for (int nt = 0; nt < 8; ++nt) {
        int col = nt * 8 + tid4 * 2;
        float2 bb = __ldg((const float2*)(bias + col));
        float2 x0 = (gr0 < M) ? *(const float2*)(x + (size_t)gr0 * DIM + col) : make_float2(0.f, 0.f);
        float2 x1 = (gr1 < M) ? *(const float2*)(x + (size_t)gr1 * DIM + col) : make_float2(0.f, 0.f);
        float v;
        v = acc[nt][0] + bb.x; v = v > 0.f ? v : (expf(v) - 1.f); y0[nt*2+0] = v + x0.x;
        v = acc[nt][1] + bb.y; v = v > 0.f ? v : (expf(v) - 1.f); y0[nt*2+1] = v + x0.y;
        v = acc[nt][2] + bb.x; v = v > 0.f ? v : (expf(v) - 1.f); y1[nt*2+0] = v + x1.x;
        v = acc[nt][3] + bb.y; v = v > 0.f ? v : (expf(v) - 1.f); y1[nt*2+1] = v + x1.y;
        s0 += y0[nt*2+0] + y0[nt*2+1]; q0 += y0[nt*2+0]*y0[nt*2+0] + y0[nt*2+1]*y0[nt*2+1];
        s1 += y1[nt*2+0] + y1[nt*2+1]; q1 += y1[nt*2+0]*y1[nt*2+0] + y1[nt*2+1]*y1[nt*2+1];
    }
    #pragma unroll
    for (int o = 1; o < 4; o <<= 1) {
        s0 += __shfl_xor_sync(0xffffffffu, s0, o);
        q0 += __shfl_xor_sync(0xffffffffu, q0, o);
        s1 += __shfl_xor_sync(0xffffffffu, s1, o);
        q1 += __shfl_xor_sync(0xffffffffu, q1, o);
    }
    float mu0  = s0 * (1.0f / 64.0f);
    float var0 = q0 * (1.0f / 64.0f) - mu0 * mu0;
    float inv0 = rsqrtf(var0 + 1e-5f);
    float mu1  = s1 * (1.0f / 64.0f);
    float var1 = q1 * (1.0f / 64.0f) - mu1 * mu1;
    float inv1 = rsqrtf(var1 + 1e-5f);
    #pragma unroll
    for (int nt = 0; nt < 8; ++nt) {
        int col = nt * 8 + tid4 * 2;
        float2 gg = __ldg((const float2*)(lng + col));
        float2 lb = __ldg((const float2*)(lnb + col));
        if (gr0 < M) {
            float2 o0;
            o0.x = (y0[nt*2+0] - mu0) * inv0 * gg.x + lb.x;
            o0.y = (y0[nt*2+1] - mu0) * inv0 * gg.y + lb.y;
            *(float2*)(out + (size_t)gr0 * DIM + col) = o0;
        }
        if (gr1 < M) {
            float2 o1;
            o1.x = (y1[nt*2+0] - mu1) * inv1 * gg.x + lb.x;
            o1.y = (y1[nt*2+1] - mu1) * inv1 * gg.y + lb.y;
            *(float2*)(out + (size_t)gr1 * DIM + col) = o1;
        }
    }
}

// ---------------- launch ----------------
extern "C" void kernel_launch(void* const* d_in, const int* in_sizes, int n_in,
                              void* d_out, int out_size)
{
    const float* x    = (const float*)d_in[0];
    const int*   ei   = (const int*)d_in[1];   // int32 [2,E]
    const float* Wlin = (const float*)d_in[2];
    const float* asrc = (const float*)d_in[3];
    const float* adst = (const float*)d_in[4];
    const float* Wout = (const float*)d_in[5];
    const float* bout = (const float*)d_in[6];
    const float* lng  = (const float*)d_in[7];
    const float* lnb  = (const float*)d_in[8];
    float*       out  = (float*)d_out;

    int n = in_sizes[0] / DIM;
    int E = in_sizes[1] / 2;
    if (n > NMAX) n = NMAX;
    if (E > EMAX) E = EMAX;

    float *p_agg, *p_ssrc, *p_sdst, *p_ealpha, *p_vv;
    uint32_t *p_wchi, *p_wclo;
    int *p_cnt, *p_off, *p_cursor, *p_esrc;
    cudaGetSymbolAddress((void**)&p_agg,    g_agg);
    cudaGetSymbolAddress((void**)&p_ssrc,   g_ssrc);
    cudaGetSymbolAddress((void**)&p_sdst,   g_sdst);
    cudaGetSymbolAddress((void**)&p_cnt,    g_cnt);
    cudaGetSymbolAddress((void**)&p_off,    g_off);
    cudaGetSymbolAddress((void**)&p_cursor, g_cursor);
    cudaGetSymbolAddress((void**)&p_esrc,   g_esrc);
    cudaGetSymbolAddress((void**)&p_ealpha, g_ealpha);
    cudaGetSymbolAddress((void**)&p_wchi,   g_wchi);
    cudaGetSymbolAddress((void**)&p_wclo,   g_wclo);
    cudaGetSymbolAddress((void**)&p_vv,     g_vv);

    cudaFuncSetAttribute(k_gemm2, cudaFuncAttributeMaxDynamicSharedMemorySize, GEMM_SMEM_B);

    // 1) dst-degree histogram
    k_hzero<<<(n + 255) / 256, 256>>>(p_cnt, n);
    k_hist <<<(E + 255) / 256, 256>>>(ei, p_cnt, E);

    // 2) fold weights (tf32 hi/lo) + score vectors
    k_prep<<<4, 256>>>(Wlin, Wout, asrc, adst, p_wchi, p_wclo, p_vv);

    // 3) per-node scores (2 threads per node)
    k_scores<<<(2 * n + 255) / 256, 256>>>(x, p_vv, p_ssrc, p_sdst, n);

    // 4) CSR offsets (vectorized scan)
    k_scan<<<1, 1024>>>(p_cnt, p_off, p_cursor, n);

    // 5) scatter edges (dst-sorted) with inline alpha
    k_scatter<<<(E + 255) / 256, 256>>>(ei, p_ssrc, p_sdst, p_cursor, p_esrc, p_ealpha, E);

    // 6) pull aggregation of raw x (2-edge pipeline)
    k_agg_x<<<(n * 32 + 255) / 256, 256>>>(p_off, p_esrc, p_ealpha, x, p_agg, n);

    // 7) out = LN(ELU(aggx @ Wc^T + b) + x) (tf32 mma)
    k_gemm2<<<(n + 127) / 128, 256, GEMM_SMEM_B>>>(p_agg, p_wchi, p_wclo, x, bout, lng, lnb, out, n);
}